// round 10
// baseline (speedup 1.0000x reference)
#include <cuda_runtime.h>
#include <cuda_bf16.h>
#include <cstdint>
#include <cstddef>

#define BN_EPS 1e-5f
#define SROW 40      // A smem row stride (floats), interleaved-swizzle layout
#define BROW 36      // B smem row stride (floats), linear layout (16B-aligned rows)

// dynamic smem layout (bytes):
//   [0, 512)                 rowIdx (128 ints)
//   [512, 512+40960)         As: 2 buffers x 128 x SROW floats
//   [41472, 41472+36864)     Bs: 2 buffers x 128 x BROW floats
#define OFF_AS 512
#define OFF_BS 41472
#define SMEM_DYN (512 + 2*128*SROW*4 + 2*128*BROW*4)

// ======================= static scratch (no allocs) =======================
__device__ float g_acc [30000 * 512];
__device__ float g_bufA[30000 * 512];
__device__ float g_bufB[30000 * 512];
__device__ float g_wt  [13450240];      // transposed tf32 weights pool
__device__ float g_sum [512];
__device__ float g_sq  [512];
__device__ float g_scale[512];
__device__ float g_shift[512];

// ======================= helpers =========================================
__device__ __forceinline__ float to_tf32(float x) {
    float y;
    asm("cvt.rna.tf32.f32 %0, %1;" : "=f"(y) : "f"(x));
    return y;
}
__device__ __forceinline__ uint32_t smem_u32(const void* p) {
    uint32_t a;
    asm("{ .reg .u64 t; cvta.to.shared.u64 t, %1; cvt.u32.u64 %0, t; }" : "=r"(a) : "l"(p));
    return a;
}
__device__ __forceinline__ void mma_tf32(float* d, const uint32_t* a, const uint32_t* b) {
    asm volatile(
        "mma.sync.aligned.m16n8k8.row.col.f32.tf32.tf32.f32 "
        "{%0,%1,%2,%3}, {%4,%5,%6,%7}, {%8,%9}, {%0,%1,%2,%3};"
        : "+f"(d[0]), "+f"(d[1]), "+f"(d[2]), "+f"(d[3])
        : "r"(a[0]), "r"(a[1]), "r"(a[2]), "r"(a[3]), "r"(b[0]), "r"(b[1]));
}
__device__ __forceinline__ void red_add_v4(float* p, float a, float b, float c, float d) {
    asm volatile("red.global.add.v4.f32 [%0], {%1, %2, %3, %4};"
                 :: "l"(p), "f"(a), "f"(b), "f"(c), "f"(d) : "memory");
}
__device__ __forceinline__ void cp_async16(uint32_t dst, const void* src, int szvalid) {
    asm volatile("cp.async.cg.shared.global [%0], [%1], 16, %2;"
                 :: "r"(dst), "l"(src), "r"(szvalid) : "memory");
}
#define CP_COMMIT()  asm volatile("cp.async.commit_group;" ::: "memory")
#define CP_WAIT(n)   asm volatile("cp.async.wait_group %0;" :: "n"(n) : "memory")

// ======================= tensor-core gather-GEMM-scatter ==================
// CTA: 256 thr (8 warps 2x4), tile 128(M) x 128(N), K-chunks of 32.
// A: gathered rows, register-prefetched 1 chunk ahead, interleaved-swizzled
//    smem (conflict-free LDS.64 fragment loads).
// B: cp.async double-buffered into linear smem (conflict-free LDS.32).
// ONE __syncthreads per chunk (race-free: cp.async for c+1 issued after
// barrier c). Epilogue: lane-pair shuffle combine -> red.global.add.v4
// (halves L2 atomic op count) or float4 direct store (dense).
__global__ __launch_bounds__(256, 2) void mma_gs_kernel(
    const float* __restrict__ A, const float* __restrict__ WT,
    const int* __restrict__ in_idx, const int* __restrict__ out_idx,
    float* __restrict__ C, int M, int Cin, int Cout)
{
    extern __shared__ char sm[];
    int*   rowIdx = (int*)sm;
    float* As     = (float*)(sm + OFF_AS);
    float* Bs     = (float*)(sm + OFF_BS);
    const uint32_t bsU = smem_u32(sm) + OFF_BS;

    const int tid  = threadIdx.x;
    const int wid  = tid >> 5;
    const int lane = tid & 31;
    const int g8   = lane >> 2;
    const int t4   = lane & 3;

    const int k     = blockIdx.z;
    const int mBase = blockIdx.x * 128;
    const int n0    = blockIdx.y * 128;
    const float* WTk = WT + (size_t)k * Cout * Cin;

    const int warpM = (wid >> 2) * 64;
    const int warpN = (wid & 3) * 32;

    if (tid < 128) {
        int g = mBase + tid;
        int ri = 0;
        if (g < M) ri = in_idx ? in_idx[(size_t)k * M + g] : g;
        rowIdx[tid] = ri;
    }
    __syncthreads();

    // per-thread A source pointers and B cp.async sources (row, 4j offsets)
    const float* aptr[4];
    const float* bptr[4];
    int bvalidrow[4];
#pragma unroll
    for (int s = 0; s < 4; ++s) {
        int gi = tid + s * 256;
        int row = gi >> 3, j = gi & 7;
        aptr[s] = A + (size_t)rowIdx[row] * Cin + 4 * j;
        int brow = n0 + row;
        bvalidrow[s] = (brow < Cout);
        bptr[s] = WTk + (size_t)(bvalidrow[s] ? brow : 0) * Cin + 4 * j;
    }

    float d[4][4][4];
#pragma unroll
    for (int mi = 0; mi < 4; mi++)
#pragma unroll
        for (int ni = 0; ni < 4; ni++)
#pragma unroll
            for (int r = 0; r < 4; r++) d[mi][ni][r] = 0.f;

    const int nc = (Cin + 31) >> 5;

    // ---- prologue: A chunk 0 -> regs; B chunk 0 -> cp.async buf0 ----
    float4 pav[4];
#pragma unroll
    for (int s = 0; s < 4; ++s) {
        int j = (tid + s * 256) & 7;
        int col = 4 * j;
        pav[s] = make_float4(0.f, 0.f, 0.f, 0.f);
        if (col < Cin) pav[s] = *(const float4*)(aptr[s]);
    }
#pragma unroll
    for (int s = 0; s < 4; ++s) {
        int gi = tid + s * 256;
        int row = gi >> 3, j = gi & 7;
        int col = 4 * j;
        int ok = (col < Cin && bvalidrow[s]) ? 16 : 0;
        cp_async16(bsU + (uint32_t)(row * BROW + 4 * j) * 4, bptr[s], ok);
    }
    CP_COMMIT();

    for (int c = 0; c < nc; ++c) {
        const int st = c & 1;

        // ---- store prefetched A chunk c into As[st] (swizzled) ----
        float* AsBuf = As + st * 128 * SROW;
#pragma unroll
        for (int s = 0; s < 4; ++s) {
            int gi  = tid + s * 256;
            int row = gi >> 3, j = gi & 7;
            int e    = (row << 1) & 6;
            int base = row * SROW + (j >> 1) * 8;
            int o    = j & 1;
            AsBuf[base + ((0 + o) ^ e)] = pav[s].x;
            AsBuf[base + ((2 + o) ^ e)] = pav[s].y;
            AsBuf[base + ((4 + o) ^ e)] = pav[s].z;
            AsBuf[base + ((6 + o) ^ e)] = pav[s].w;
        }

        // ---- prefetch A chunk c+1 into registers ----
        if (c + 1 < nc) {
            const int c1 = (c + 1) << 5;
#pragma unroll
            for (int s = 0; s < 4; ++s) {
                int j = (tid + s * 256) & 7;
                int col = c1 + 4 * j;
                pav[s] = make_float4(0.f, 0.f, 0.f, 0.f);
                if (col < Cin) pav[s] = *(const float4*)(aptr[s] + c1);
            }
        }

        // ---- complete B chunk c, publish everything CTA-wide ----
        CP_WAIT(0);
        __syncthreads();

        // ---- safe to issue B chunk c+1 into buffer st^1 now ----
        if (c + 1 < nc) {
            const int c1 = (c + 1) << 5;
#pragma unroll
            for (int s = 0; s < 4; ++s) {
                int gi = tid + s * 256;
                int row = gi >> 3, j = gi & 7;
                int col = c1 + 4 * j;
                int ok = (col < Cin && bvalidrow[s]) ? 16 : 0;
                cp_async16(bsU + (uint32_t)((st ^ 1) * 128 * BROW + row * BROW + 4 * j) * 4,
                           bptr[s] + c1, ok);
            }
            CP_COMMIT();
        }

        // ---- 4 k8 MMA steps (covers chunk c+1's cp.async latency) ----
        const float* BsBuf = Bs + st * 128 * BROW;
#pragma unroll
        for (int kk = 0; kk < 4; ++kk) {
            const int kb = kk << 3;
            uint32_t a[4][4];
#pragma unroll
            for (int mi = 0; mi < 4; mi++) {
                int r = warpM + mi * 16 + g8;
                int e = (r << 1) & 6;
                int off = r * SROW + kb + ((2 * t4) ^ e);
                float2 v0 = *(const float2*)&AsBuf[off];
                float2 v1 = *(const float2*)&AsBuf[off + 8 * SROW];
                a[mi][0] = __float_as_uint(v0.x);
                a[mi][2] = __float_as_uint(v0.y);
                a[mi][1] = __float_as_uint(v1.x);
                a[mi][3] = __float_as_uint(v1.y);
            }
            uint32_t b[4][2];
#pragma unroll
            for (int ni = 0; ni < 4; ni++) {
                int n = warpN + ni * 8 + g8;
                b[ni][0] = __float_as_uint(BsBuf[n * BROW + kb + t4]);
                b[ni][1] = __float_as_uint(BsBuf[n * BROW + kb + t4 + 4]);
            }
#pragma unroll
            for (int mi = 0; mi < 4; mi++)
#pragma unroll
                for (int ni = 0; ni < 4; ni++)
                    mma_tf32(d[mi][ni], a[mi], b[ni]);
        }
    }

    // ---- epilogue: lane-pair combine -> red.v4 scatter / float4 store ----
    // lanes (t4, t4^1) hold adjacent col pairs of the same row; after two
    // shfl_xor(1), even-t4 lanes own 4 contiguous cols (16B-aligned since
    // cols are 4-aligned and Cout % 4 == 0).
#pragma unroll
    for (int mi = 0; mi < 4; mi++) {
        int r0 = mBase + warpM + mi * 16 + g8;
#pragma unroll
        for (int half = 0; half < 2; half++) {
            int rr = r0 + half * 8;
            size_t orow = 0;
            if (rr < M)
                orow = out_idx ? (size_t)out_idx[(size_t)k * M + rr] : (size_t)rr;
            float* crow = C + orow * Cout;
#pragma unroll
            for (int ni = 0; ni < 4; ni++) {
                float v0 = d[mi][ni][half * 2 + 0];
                float v1 = d[mi][ni][half * 2 + 1];
                float p0 = __shfl_xor_sync(0xffffffffu, v0, 1);
                float p1 = __shfl_xor_sync(0xffffffffu, v1, 1);
                if (rr < M && (t4 & 1) == 0) {
                    int col = n0 + warpN + ni * 8 + (t4 << 1);   // t4=0 -> +0, t4=2 -> +4
                    if (col < Cout) {
                        if (out_idx) red_add_v4(crow + col, v0, v1, p0, p1);
                        else *(float4*)(crow + col) = make_float4(v0, v1, p0, p1);
                    }
                }
            }
        }
    }
}

// ===== weight transpose [K][Cin][Cout] -> [K][Cout][Cin], tf32-rounded ====
__global__ void transpose_kernel(const float* __restrict__ in, float* __restrict__ out,
                                 int R, int Ccol)
{
    __shared__ float t[32][33];
    const size_t koff = (size_t)blockIdx.z * R * Ccol;
    const float* ink = in + koff;
    float* outk = out + koff;
    int c0 = blockIdx.x * 32, r0 = blockIdx.y * 32;
    for (int i = threadIdx.y; i < 32; i += 8) {
        int r = r0 + i, c = c0 + threadIdx.x;
        t[i][threadIdx.x] = (r < R && c < Ccol) ? ink[(size_t)r * Ccol + c] : 0.f;
    }
    __syncthreads();
    for (int i = threadIdx.y; i < 32; i += 8) {
        int cc = c0 + i, rr = r0 + threadIdx.x;
        if (cc < Ccol && rr < R) outk[(size_t)cc * R + rr] = to_tf32(t[threadIdx.x][i]);
    }
}

// ======================= tf32 convert (for f3) ===========================
__global__ void cvt_kernel(const float* __restrict__ in, float* __restrict__ out, int n)
{
    int i = blockIdx.x * blockDim.x + threadIdx.x;
    if (i < n) out[i] = to_tf32(in[i]);
}

// ======================= BN kernels ======================================
__global__ void stats_kernel(const float* __restrict__ x, int N, int C,
                             float* __restrict__ sum, float* __restrict__ sq)
{
    extern __shared__ float s[];
    for (int i = threadIdx.x; i < 2 * C; i += blockDim.x) s[i] = 0.f;
    __syncthreads();
    size_t total = (size_t)N * C;
    for (size_t i = (size_t)blockIdx.x * blockDim.x + threadIdx.x; i < total;
         i += (size_t)gridDim.x * blockDim.x) {
        float v = x[i];
        int c = (int)(i % (size_t)C);
        atomicAdd(&s[c], v);
        atomicAdd(&s[C + c], v * v);
    }
    __syncthreads();
    for (int c = threadIdx.x; c < C; c += blockDim.x) {
        atomicAdd(&sum[c], s[c]);
        atomicAdd(&sq[c],  s[C + c]);
    }
}

__global__ void bnparam_kernel(const float* __restrict__ sum, const float* __restrict__ sq,
                               const float* __restrict__ gamma, const float* __restrict__ beta,
                               int N, int C,
                               float* __restrict__ scale, float* __restrict__ shift)
{
    int c = blockIdx.x * blockDim.x + threadIdx.x;
    if (c < C) {
        float invN = 1.f / (float)N;
        float m = sum[c] * invN;
        float v = sq[c] * invN - m * m;
        float sc = gamma[c] * rsqrtf(v + BN_EPS);
        scale[c] = sc;
        shift[c] = beta[c] - m * sc;
    }
}

// do_cvt: round output to tf32 (it feeds a GEMM next). Final layer: 0.
__global__ void bnapply_kernel(const float* __restrict__ x, int N, int C, int ostride,
                               const float* __restrict__ scale, const float* __restrict__ shift,
                               float* __restrict__ out, int do_cvt)
{
    size_t total = (size_t)N * C;
    for (size_t i = (size_t)blockIdx.x * blockDim.x + threadIdx.x; i < total;
         i += (size_t)gridDim.x * blockDim.x) {
        int c = (int)(i % (size_t)C);
        size_t r = i / (size_t)C;
        float v = fmaxf(fmaf(x[i], scale[c], shift[c]), 0.f);
        out[r * (size_t)ostride + c] = do_cvt ? to_tf32(v) : v;
    }
}

__global__ void copyskip_kernel(const float* __restrict__ f, int N, int Cf,
                                int ostride, int coff, float* __restrict__ out)
{
    size_t total = (size_t)N * Cf;
    for (size_t i = (size_t)blockIdx.x * blockDim.x + threadIdx.x; i < total;
         i += (size_t)gridDim.x * blockDim.x) {
        int c = (int)(i % (size_t)Cf);
        size_t r = i / (size_t)Cf;
        out[r * (size_t)ostride + coff + c] = to_tf32(f[i]);
    }
}

// ==========================================================================
extern "C" void kernel_launch(void* const* d_in, const int* in_sizes, int n_in,
                              void* d_out, int out_size)
{
    (void)in_sizes; (void)n_in; (void)out_size;

    const float* f0    = (const float*)d_in[0];
    const float* f1    = (const float*)d_in[1];
    const float* f2    = (const float*)d_in[2];
    const float* f3    = (const float*)d_in[3];
    const float* W_up2 = (const float*)d_in[4];
    const float* W_up1 = (const float*)d_in[5];
    const float* W_up0 = (const float*)d_in[6];
    const float* W_s0  = (const float*)d_in[7];
    const float* W_s1  = (const float*)d_in[8];
    const float* W_s2  = (const float*)d_in[9];
    const float* g_up2 = (const float*)d_in[10]; const float* b_up2 = (const float*)d_in[11];
    const float* g_up1 = (const float*)d_in[12]; const float* b_up1 = (const float*)d_in[13];
    const float* g_up0 = (const float*)d_in[14]; const float* b_up0 = (const float*)d_in[15];
    const float* g_s0  = (const float*)d_in[16]; const float* b_s0  = (const float*)d_in[17];
    const float* g_s1  = (const float*)d_in[18]; const float* b_s1  = (const float*)d_in[19];
    const float* g_s2  = (const float*)d_in[20]; const float* b_s2  = (const float*)d_in[21];
    const int* up2_in = (const int*)d_in[22]; const int* up2_out = (const int*)d_in[23];
    const int* up1_in = (const int*)d_in[24]; const int* up1_out = (const int*)d_in[25];
    const int* up0_in = (const int*)d_in[26]; const int* up0_out = (const int*)d_in[27];
    const int* sm0_in = (const int*)d_in[28]; const int* sm0_out = (const int*)d_in[29];
    const int* sm1_in = (const int*)d_in[30]; const int* sm1_out = (const int*)d_in[31];

    float *acc, *bufA, *bufB, *wt, *sum, *sq, *scale, *shift;
    cudaGetSymbolAddress((void**)&acc,   g_acc);
    cudaGetSymbolAddress((void**)&bufA,  g_bufA);
    cudaGetSymbolAddress((void**)&bufB,  g_bufB);
    cudaGetSymbolAddress((void**)&wt,    g_wt);
    cudaGetSymbolAddress((void**)&sum,   g_sum);
    cudaGetSymbolAddress((void**)&sq,    g_sq);
    cudaGetSymbolAddress((void**)&scale, g_scale);
    cudaGetSymbolAddress((void**)&shift, g_shift);

    cudaFuncSetAttribute(mma_gs_kernel,
                         cudaFuncAttributeMaxDynamicSharedMemorySize, SMEM_DYN);

    const int N0 = 30000, N1 = 12000, N2 = 5000;
    const int K = 27;

    // --- transpose all weights into pool (tf32-rounded) ---
    float* wt_up2 = wt;
    float* wt_up1 = wt_up2 + (size_t)27 * 128 * 128;
    float* wt_up0 = wt_up1 + (size_t)27 * 192 * 192;
    float* wt_s0  = wt_up0 + (size_t)27 * 224 * 224;
    float* wt_s1  = wt_s0  + (size_t)27 * 240 * 512;
    float* wt_s2  = wt_s1  + (size_t)27 * 512 * 512;

    auto tlaunch = [&](const float* W, float* WT, int Cin, int Cout, int kk) {
        dim3 tg((Cout + 31) / 32, (Cin + 31) / 32, kk);
        transpose_kernel<<<tg, dim3(32, 8), 0, 0>>>(W, WT, Cin, Cout);
    };
    tlaunch(W_up2, wt_up2, 128, 128, K);
    tlaunch(W_up1, wt_up1, 192, 192, K);
    tlaunch(W_up0, wt_up0, 224, 224, K);
    tlaunch(W_s0,  wt_s0,  240, 512, K);
    tlaunch(W_s1,  wt_s1,  512, 512, K);
    tlaunch(W_s2,  wt_s2,  512, 512, 1);

    // f3 -> tf32 copy in bufB (bufB not used until up1's output)
    cvt_kernel<<<(2000 * 128 + 255) / 256, 256, 0, 0>>>(f3, bufB, 2000 * 128);

    auto layer = [&](const float* A, const float* WT,
                     const int* ii, const int* oi,
                     int M, int Cin, int Cout, int Nout,
                     const float* gamma, const float* beta,
                     float* outbuf, int ostride,
                     const float* skip, int Cskip, int skip_N, int do_cvt)
    {
        bool sparse = (oi != nullptr);
        float* dst = sparse ? acc : outbuf;   // dense final layer stores direct
        if (sparse)
            cudaMemsetAsync(acc, 0, (size_t)Nout * Cout * sizeof(float), 0);
        cudaMemsetAsync(sum, 0, Cout * sizeof(float), 0);
        cudaMemsetAsync(sq,  0, Cout * sizeof(float), 0);

        dim3 grid((M + 127) / 128, (Cout + 127) / 128, sparse ? K : 1);
        mma_gs_kernel<<<grid, 256, SMEM_DYN, 0>>>(A, WT, ii, oi, dst, M, Cin, Cout);

        stats_kernel<<<592, 256, 2 * Cout * sizeof(float), 0>>>(dst, Nout, Cout, sum, sq);
        bnparam_kernel<<<2, 256, 0, 0>>>(sum, sq, gamma, beta, Nout, Cout, scale, shift);
        bnapply_kernel<<<592, 256, 0, 0>>>(dst, Nout, Cout, ostride, scale, shift, outbuf, do_cvt);
        if (skip)
            copyskip_kernel<<<256, 256, 0, 0>>>(skip, skip_N, Cskip, ostride, Cout, outbuf);
    };

    // up2: tf32(f3) -> N2 (Cout 128), concat f2(64) -> bufA[5000,192]
    layer(bufB, wt_up2, up2_in, up2_out, 1600, 128, 128, N2, g_up2, b_up2, bufA, 192, f2, 64, N2, 1);
    // up1: bufA -> N1 (Cout 192), concat f1(32) -> bufB[12000,224]
    layer(bufA, wt_up1, up1_in, up1_out, 4000, 192, 192, N1, g_up1, b_up1, bufB, 224, f1, 32, N1, 1);
    // up0: bufB -> N0 (Cout 224), concat f0(16) -> bufA[30000,240]
    layer(bufB, wt_up0, up0_in, up0_out, 10000, 224, 224, N0, g_up0, b_up0, bufA, 240, f0, 16, N0, 1);
    // s0: bufA[30000,240] -> N0 (Cout 512) -> bufB
    layer(bufA, wt_s0, sm0_in, sm0_out, 10000, 240, 512, N0, g_s0, b_s0, bufB, 512, nullptr, 0, 0, 1);
    // s1: bufB -> N0 (Cout 512) -> bufA
    layer(bufB, wt_s1, sm1_in, sm1_out, 10000, 512, 512, N0, g_s1, b_s1, bufA, 512, nullptr, 0, 0, 1);
    // s2: dense GEMM bufA @ W_s2 -> d_out (fp32 output, no cvt)
    layer(bufA, wt_s2, nullptr, nullptr, N0, 512, 512, N0, g_s2, b_s2, (float*)d_out, 512, nullptr, 0, 0, 0);
}

// round 11
// speedup vs baseline: 1.5222x; 1.5222x over previous
#include <cuda_runtime.h>
#include <cuda_fp16.h>
#include <cstdint>
#include <cstddef>

#define BN_EPS 1e-5f
#define HROW 40      // smem row stride in halfs (80 B, 16B-aligned)

// dynamic smem (bytes): [0,512) rowIdx; [512,+20480) As x2; [20992,+20480) Bs x2
#define OFF_AS 512
#define OFF_BS 20992
#define SMEM_DYN (20992 + 20480)

// ======================= static scratch (no allocs) =======================
__device__ float  g_acc [30000 * 512];
__device__ __half g_hA  [30000 * 512];
__device__ __half g_hB  [30000 * 512];
__device__ __half g_wth [13450240];     // transposed fp16 weights pool
__device__ float  g_sum [512];
__device__ float  g_sq  [512];
__device__ float  g_scale[512];
__device__ float  g_shift[512];

// ======================= helpers =========================================
__device__ __forceinline__ uint32_t smem_u32(const void* p) {
    uint32_t a;
    asm("{ .reg .u64 t; cvta.to.shared.u64 t, %1; cvt.u32.u64 %0, t; }" : "=r"(a) : "l"(p));
    return a;
}
__device__ __forceinline__ void mma_f16(float* d, const uint32_t* a, const uint32_t* b) {
    asm volatile(
        "mma.sync.aligned.m16n8k16.row.col.f32.f16.f16.f32 "
        "{%0,%1,%2,%3}, {%4,%5,%6,%7}, {%8,%9}, {%0,%1,%2,%3};"
        : "+f"(d[0]), "+f"(d[1]), "+f"(d[2]), "+f"(d[3])
        : "r"(a[0]), "r"(a[1]), "r"(a[2]), "r"(a[3]), "r"(b[0]), "r"(b[1]));
}
__device__ __forceinline__ void red_add_v4(float* p, float a, float b, float c, float d) {
    asm volatile("red.global.add.v4.f32 [%0], {%1, %2, %3, %4};"
                 :: "l"(p), "f"(a), "f"(b), "f"(c), "f"(d) : "memory");
}
__device__ __forceinline__ void cp_async16(uint32_t dst, const void* src, int szvalid) {
    asm volatile("cp.async.cg.shared.global [%0], [%1], 16, %2;"
                 :: "r"(dst), "l"(src), "r"(szvalid) : "memory");
}
#define CP_COMMIT()  asm volatile("cp.async.commit_group;" ::: "memory")
#define CP_WAIT(n)   asm volatile("cp.async.wait_group %0;" :: "n"(n) : "memory")

// ======================= fp16 tensor-core gather-GEMM-scatter =============
// CTA: 256 thr (8 warps 2x4), tile 128(M) x 128(N), K-chunks of 32 halfs.
// A: gathered half rows, register-prefetched 1 chunk ahead (uint4 = 8 halfs),
//    plain layout row*HROW, conflict-free half2 fragment loads.
// B: cp.async double-buffered, same layout.
// One __syncthreads per chunk; cp.async for c+1 issued after barrier c.
// Epilogue: lane-pair combine -> red.v4 scatter / float4 store (fp32).
__global__ __launch_bounds__(256, 2) void mma_gs_kernel(
    const __half* __restrict__ A, const __half* __restrict__ WT,
    const int* __restrict__ in_idx, const int* __restrict__ out_idx,
    float* __restrict__ C, int M, int Cin, int Cout)
{
    extern __shared__ char sm[];
    int*      rowIdx = (int*)sm;
    uint32_t* AsW    = (uint32_t*)(sm + OFF_AS);   // word view (half2)
    uint32_t* BsW    = (uint32_t*)(sm + OFF_BS);
    const uint32_t bsU = smem_u32(sm) + OFF_BS;

    const int tid  = threadIdx.x;
    const int wid  = tid >> 5;
    const int lane = tid & 31;
    const int g8   = lane >> 2;
    const int t4   = lane & 3;

    const int k     = blockIdx.z;
    const int mBase = blockIdx.x * 128;
    const int n0    = blockIdx.y * 128;
    const __half* WTk = WT + (size_t)k * Cout * Cin;

    const int warpM = (wid >> 2) * 64;
    const int warpN = (wid & 3) * 32;

    if (tid < 128) {
        int g = mBase + tid;
        int ri = 0;
        if (g < M) ri = in_idx ? in_idx[(size_t)k * M + g] : g;
        rowIdx[tid] = ri;
    }
    __syncthreads();

    // per-thread source pointers: s in {0,1}; gi = tid + 256 s;
    // row = gi>>2 (0..127), j = gi&3 (16B slot), col = 8 j halfs
    const __half* aptr[2];
    const __half* bptr[2];
    int bvalid[2];
#pragma unroll
    for (int s = 0; s < 2; ++s) {
        int gi = tid + s * 256;
        int row = gi >> 2, j = gi & 3;
        aptr[s] = A + (size_t)rowIdx[row] * Cin + 8 * j;
        int brow = n0 + row;
        bvalid[s] = (brow < Cout);
        bptr[s] = WTk + (size_t)(bvalid[s] ? brow : 0) * Cin + 8 * j;
    }

    float d[4][4][4];
#pragma unroll
    for (int mi = 0; mi < 4; mi++)
#pragma unroll
        for (int ni = 0; ni < 4; ni++)
#pragma unroll
            for (int r = 0; r < 4; r++) d[mi][ni][r] = 0.f;

    const int nc = (Cin + 31) >> 5;

    // ---- prologue: A chunk 0 -> regs; B chunk 0 -> cp.async buf0 ----
    uint4 pav[2];
#pragma unroll
    for (int s = 0; s < 2; ++s) {
        int gi = tid + s * 256;
        int j = gi & 3;
        pav[s] = make_uint4(0u, 0u, 0u, 0u);
        if (8 * j < Cin) pav[s] = *(const uint4*)(aptr[s]);
    }
#pragma unroll
    for (int s = 0; s < 2; ++s) {
        int gi = tid + s * 256;
        int row = gi >> 2, j = gi & 3;
        int ok = (8 * j < Cin && bvalid[s]) ? 16 : 0;
        cp_async16(bsU + (uint32_t)(row * 80 + 16 * j), bptr[s], ok);
    }
    CP_COMMIT();

    for (int c = 0; c < nc; ++c) {
        const int st = c & 1;
        const int stoff = st * 128 * (HROW / 2);   // word offset of buffer

        // ---- store prefetched A chunk c ----
#pragma unroll
        for (int s = 0; s < 2; ++s) {
            int gi = tid + s * 256;
            int row = gi >> 2, j = gi & 3;
            *(uint4*)&AsW[stoff + row * 20 + 4 * j] = pav[s];
        }

        // ---- prefetch A chunk c+1 into registers ----
        if (c + 1 < nc) {
            const int c1 = (c + 1) << 5;
#pragma unroll
            for (int s = 0; s < 2; ++s) {
                int gi = tid + s * 256;
                int j = gi & 3;
                int col = c1 + 8 * j;
                pav[s] = make_uint4(0u, 0u, 0u, 0u);
                if (col < Cin) pav[s] = *(const uint4*)(aptr[s] + c1);
            }
        }

        // ---- complete B chunk c, publish ----
        CP_WAIT(0);
        __syncthreads();

        // ---- safe now: issue B chunk c+1 into buffer st^1 ----
        if (c + 1 < nc) {
            const int c1 = (c + 1) << 5;
#pragma unroll
            for (int s = 0; s < 2; ++s) {
                int gi = tid + s * 256;
                int row = gi >> 2, j = gi & 3;
                int ok = (c1 + 8 * j < Cin && bvalid[s]) ? 16 : 0;
                cp_async16(bsU + (uint32_t)((st ^ 1) * 10240 + row * 80 + 16 * j),
                           bptr[s] + c1, ok);
            }
            CP_COMMIT();
        }

        // ---- 2 k16 MMA steps ----
        const uint32_t* AsB = AsW + stoff;
        const uint32_t* BsB = BsW + stoff;
#pragma unroll
        for (int kk = 0; kk < 2; ++kk) {
            const int kw = kk * 8;           // k16 step = 16 halfs = 8 words
            uint32_t a[4][4];
#pragma unroll
            for (int mi = 0; mi < 4; mi++) {
                int r = warpM + mi * 16 + g8;
                int w = r * 20 + kw + t4;
                a[mi][0] = AsB[w];
                a[mi][1] = AsB[w + 8 * 20];
                a[mi][2] = AsB[w + 4];
                a[mi][3] = AsB[w + 8 * 20 + 4];
            }
            uint32_t b[4][2];
#pragma unroll
            for (int ni = 0; ni < 4; ni++) {
                int n = warpN + ni * 8 + g8;
                int w = n * 20 + kw + t4;
                b[ni][0] = BsB[w];
                b[ni][1] = BsB[w + 4];
            }
#pragma unroll
            for (int mi = 0; mi < 4; mi++)
#pragma unroll
                for (int ni = 0; ni < 4; ni++)
                    mma_f16(d[mi][ni], a[mi], b[ni]);
        }
    }

    // ---- epilogue: lane-pair combine -> red.v4 scatter / float4 store ----
#pragma unroll
    for (int mi = 0; mi < 4; mi++) {
        int r0 = mBase + warpM + mi * 16 + g8;
#pragma unroll
        for (int half = 0; half < 2; half++) {
            int rr = r0 + half * 8;
            size_t orow = 0;
            if (rr < M)
                orow = out_idx ? (size_t)out_idx[(size_t)k * M + rr] : (size_t)rr;
            float* crow = C + orow * Cout;
#pragma unroll
            for (int ni = 0; ni < 4; ni++) {
                float v0 = d[mi][ni][half * 2 + 0];
                float v1 = d[mi][ni][half * 2 + 1];
                float p0 = __shfl_xor_sync(0xffffffffu, v0, 1);
                float p1 = __shfl_xor_sync(0xffffffffu, v1, 1);
                if (rr < M && (t4 & 1) == 0) {
                    int col = n0 + warpN + ni * 8 + (t4 << 1);
                    if (col < Cout) {
                        if (out_idx) red_add_v4(crow + col, v0, v1, p0, p1);
                        else *(float4*)(crow + col) = make_float4(v0, v1, p0, p1);
                    }
                }
            }
        }
    }
}

// ===== weight transpose [K][Cin][Cout] -> [K][Cout][Cin], fp16-rounded ====
__global__ void transpose_kernel(const float* __restrict__ in, __half* __restrict__ out,
                                 int R, int Ccol)
{
    __shared__ float t[32][33];
    const size_t koff = (size_t)blockIdx.z * R * Ccol;
    const float* ink = in + koff;
    __half* outk = out + koff;
    int c0 = blockIdx.x * 32, r0 = blockIdx.y * 32;
    for (int i = threadIdx.y; i < 32; i += 8) {
        int r = r0 + i, c = c0 + threadIdx.x;
        t[i][threadIdx.x] = (r < R && c < Ccol) ? ink[(size_t)r * Ccol + c] : 0.f;
    }
    __syncthreads();
    for (int i = threadIdx.y; i < 32; i += 8) {
        int cc = c0 + i, rr = r0 + threadIdx.x;
        if (cc < Ccol && rr < R) outk[(size_t)cc * R + rr] = __float2half_rn(t[threadIdx.x][i]);
    }
}

// ======================= f32 -> f16 convert (for f3) =====================
__global__ void cvt_kernel(const float* __restrict__ in, __half* __restrict__ out, int n)
{
    int i = blockIdx.x * blockDim.x + threadIdx.x;
    if (i < n) out[i] = __float2half_rn(in[i]);
}

// ======================= BN kernels ======================================
__global__ void stats_kernel(const float* __restrict__ x, int N, int C,
                             float* __restrict__ sum, float* __restrict__ sq)
{
    extern __shared__ float s[];
    for (int i = threadIdx.x; i < 2 * C; i += blockDim.x) s[i] = 0.f;
    __syncthreads();
    size_t total = (size_t)N * C;
    for (size_t i = (size_t)blockIdx.x * blockDim.x + threadIdx.x; i < total;
         i += (size_t)gridDim.x * blockDim.x) {
        float v = x[i];
        int c = (int)(i % (size_t)C);
        atomicAdd(&s[c], v);
        atomicAdd(&s[C + c], v * v);
    }
    __syncthreads();
    for (int c = threadIdx.x; c < C; c += blockDim.x) {
        atomicAdd(&sum[c], s[c]);
        atomicAdd(&sq[c],  s[C + c]);
    }
}

__global__ void bnparam_kernel(const float* __restrict__ sum, const float* __restrict__ sq,
                               const float* __restrict__ gamma, const float* __restrict__ beta,
                               int N, int C,
                               float* __restrict__ scale, float* __restrict__ shift)
{
    int c = blockIdx.x * blockDim.x + threadIdx.x;
    if (c < C) {
        float invN = 1.f / (float)N;
        float m = sum[c] * invN;
        float v = sq[c] * invN - m * m;
        float sc = gamma[c] * rsqrtf(v + BN_EPS);
        scale[c] = sc;
        shift[c] = beta[c] - m * sc;
    }
}

// normalize+ReLU -> fp16 concat-strided buffer (feeds next GEMM)
__global__ void bnapply_h_kernel(const float* __restrict__ x, int N, int C, int ostride,
                                 const float* __restrict__ scale, const float* __restrict__ shift,
                                 __half* __restrict__ out)
{
    size_t total = (size_t)N * C;
    for (size_t i = (size_t)blockIdx.x * blockDim.x + threadIdx.x; i < total;
         i += (size_t)gridDim.x * blockDim.x) {
        int c = (int)(i % (size_t)C);
        size_t r = i / (size_t)C;
        float v = fmaxf(fmaf(x[i], scale[c], shift[c]), 0.f);
        out[r * (size_t)ostride + c] = __float2half_rn(v);
    }
}

// final layer: normalize+ReLU in place, fp32 out
__global__ void bnapply_f_kernel(float* __restrict__ x, int N, int C,
                                 const float* __restrict__ scale, const float* __restrict__ shift)
{
    size_t total = (size_t)N * C;
    for (size_t i = (size_t)blockIdx.x * blockDim.x + threadIdx.x; i < total;
         i += (size_t)gridDim.x * blockDim.x) {
        int c = (int)(i % (size_t)C);
        x[i] = fmaxf(fmaf(x[i], scale[c], shift[c]), 0.f);
    }
}

__global__ void copyskip_kernel(const float* __restrict__ f, int N, int Cf,
                                int ostride, int coff, __half* __restrict__ out)
{
    size_t total = (size_t)N * Cf;
    for (size_t i = (size_t)blockIdx.x * blockDim.x + threadIdx.x; i < total;
         i += (size_t)gridDim.x * blockDim.x) {
        int c = (int)(i % (size_t)Cf);
        size_t r = i / (size_t)Cf;
        out[r * (size_t)ostride + coff + c] = __float2half_rn(f[i]);
    }
}

// ==========================================================================
extern "C" void kernel_launch(void* const* d_in, const int* in_sizes, int n_in,
                              void* d_out, int out_size)
{
    (void)in_sizes; (void)n_in; (void)out_size;

    const float* f0    = (const float*)d_in[0];
    const float* f1    = (const float*)d_in[1];
    const float* f2    = (const float*)d_in[2];
    const float* f3    = (const float*)d_in[3];
    const float* W_up2 = (const float*)d_in[4];
    const float* W_up1 = (const float*)d_in[5];
    const float* W_up0 = (const float*)d_in[6];
    const float* W_s0  = (const float*)d_in[7];
    const float* W_s1  = (const float*)d_in[8];
    const float* W_s2  = (const float*)d_in[9];
    const float* g_up2 = (const float*)d_in[10]; const float* b_up2 = (const float*)d_in[11];
    const float* g_up1 = (const float*)d_in[12]; const float* b_up1 = (const float*)d_in[13];
    const float* g_up0 = (const float*)d_in[14]; const float* b_up0 = (const float*)d_in[15];
    const float* g_s0  = (const float*)d_in[16]; const float* b_s0  = (const float*)d_in[17];
    const float* g_s1  = (const float*)d_in[18]; const float* b_s1  = (const float*)d_in[19];
    const float* g_s2  = (const float*)d_in[20]; const float* b_s2  = (const float*)d_in[21];
    const int* up2_in = (const int*)d_in[22]; const int* up2_out = (const int*)d_in[23];
    const int* up1_in = (const int*)d_in[24]; const int* up1_out = (const int*)d_in[25];
    const int* up0_in = (const int*)d_in[26]; const int* up0_out = (const int*)d_in[27];
    const int* sm0_in = (const int*)d_in[28]; const int* sm0_out = (const int*)d_in[29];
    const int* sm1_in = (const int*)d_in[30]; const int* sm1_out = (const int*)d_in[31];

    float *acc, *sum, *sq, *scale, *shift;
    __half *hA, *hB, *wth;
    cudaGetSymbolAddress((void**)&acc,   g_acc);
    cudaGetSymbolAddress((void**)&hA,    g_hA);
    cudaGetSymbolAddress((void**)&hB,    g_hB);
    cudaGetSymbolAddress((void**)&wth,   g_wth);
    cudaGetSymbolAddress((void**)&sum,   g_sum);
    cudaGetSymbolAddress((void**)&sq,    g_sq);
    cudaGetSymbolAddress((void**)&scale, g_scale);
    cudaGetSymbolAddress((void**)&shift, g_shift);

    cudaFuncSetAttribute(mma_gs_kernel,
                         cudaFuncAttributeMaxDynamicSharedMemorySize, SMEM_DYN);

    const int N0 = 30000, N1 = 12000, N2 = 5000;
    const int K = 27;

    // --- transpose all weights into fp16 pool ---
    __half* wt_up2 = wth;
    __half* wt_up1 = wt_up2 + (size_t)27 * 128 * 128;
    __half* wt_up0 = wt_up1 + (size_t)27 * 192 * 192;
    __half* wt_s0  = wt_up0 + (size_t)27 * 224 * 224;
    __half* wt_s1  = wt_s0  + (size_t)27 * 240 * 512;
    __half* wt_s2  = wt_s1  + (size_t)27 * 512 * 512;

    auto tlaunch = [&](const float* W, __half* WT, int Cin, int Cout, int kk) {
        dim3 tg((Cout + 31) / 32, (Cin + 31) / 32, kk);
        transpose_kernel<<<tg, dim3(32, 8), 0, 0>>>(W, WT, Cin, Cout);
    };
    tlaunch(W_up2, wt_up2, 128, 128, K);
    tlaunch(W_up1, wt_up1, 192, 192, K);
    tlaunch(W_up0, wt_up0, 224, 224, K);
    tlaunch(W_s0,  wt_s0,  240, 512, K);
    tlaunch(W_s1,  wt_s1,  512, 512, K);
    tlaunch(W_s2,  wt_s2,  512, 512, 1);

    // f3 -> fp16 in hB (hB not written again until up1's output)
    cvt_kernel<<<(2000 * 128 + 255) / 256, 256, 0, 0>>>(f3, hB, 2000 * 128);

    auto layer = [&](const __half* A, const __half* WT,
                     const int* ii, const int* oi,
                     int M, int Cin, int Cout, int Nout,
                     const float* gamma, const float* beta,
                     __half* outbuf, int ostride,       // fp16 output (or null for final)
                     float* foutbuf,                    // fp32 output (final layer)
                     const float* skip, int Cskip, int skip_N)
    {
        bool sparse = (oi != nullptr);
        float* dst = sparse ? acc : foutbuf;  // dense final stores fp32 direct
        if (sparse)
            cudaMemsetAsync(acc, 0, (size_t)Nout * Cout * sizeof(float), 0);
        cudaMemsetAsync(sum, 0, Cout * sizeof(float), 0);
        cudaMemsetAsync(sq,  0, Cout * sizeof(float), 0);

        dim3 grid((M + 127) / 128, (Cout + 127) / 128, sparse ? K : 1);
        mma_gs_kernel<<<grid, 256, SMEM_DYN, 0>>>(A, WT, ii, oi, dst, M, Cin, Cout);

        stats_kernel<<<592, 256, 2 * Cout * sizeof(float), 0>>>(dst, Nout, Cout, sum, sq);
        bnparam_kernel<<<2, 256, 0, 0>>>(sum, sq, gamma, beta, Nout, Cout, scale, shift);
        if (outbuf) {
            bnapply_h_kernel<<<592, 256, 0, 0>>>(dst, Nout, Cout, ostride, scale, shift, outbuf);
            if (skip)
                copyskip_kernel<<<256, 256, 0, 0>>>(skip, skip_N, Cskip, ostride, Cout, outbuf);
        } else {
            bnapply_f_kernel<<<592, 256, 0, 0>>>(dst, Nout, Cout, scale, shift);
        }
    };

    // up2: f3(h) -> N2 (Cout 128), concat f2(64) -> hA[5000,192]
    layer(hB, wt_up2, up2_in, up2_out, 1600, 128, 128, N2, g_up2, b_up2, hA, 192, nullptr, f2, 64, N2);
    // up1: hA -> N1 (Cout 192), concat f1(32) -> hB[12000,224]
    layer(hA, wt_up1, up1_in, up1_out, 4000, 192, 192, N1, g_up1, b_up1, hB, 224, nullptr, f1, 32, N1);
    // up0: hB -> N0 (Cout 224), concat f0(16) -> hA[30000,240]
    layer(hB, wt_up0, up0_in, up0_out, 10000, 224, 224, N0, g_up0, b_up0, hA, 240, nullptr, f0, 16, N0);
    // s0: hA[30000,240] -> N0 (Cout 512) -> hB
    layer(hA, wt_s0, sm0_in, sm0_out, 10000, 240, 512, N0, g_s0, b_s0, hB, 512, nullptr, nullptr, 0, 0);
    // s1: hB -> N0 (Cout 512) -> hA
    layer(hB, wt_s1, sm1_in, sm1_out, 10000, 512, 512, N0, g_s1, b_s1, hA, 512, nullptr, nullptr, 0, 0);
    // s2: dense GEMM hA @ W_s2 -> d_out (fp32), BN+ReLU in place
    layer(hA, wt_s2, nullptr, nullptr, N0, 512, 512, N0, g_s2, b_s2, nullptr, 512, (float*)d_out, nullptr, 0, 0);
}